// round 17
// baseline (speedup 1.0000x reference)
#include <cuda_runtime.h>
#include <cuda_fp16.h>

#define N_NODES 12288
#define DIM 64
#define N_EDGES 262144
#define EPS_F 0.01f
#define BLK 256
#define BLOCKS_PER_SM 6
#define GRID (148 * BLOCKS_PER_SM)   // 888 blocks, co-residency guaranteed

// Repacked storage: r rows compressed to fp16 (64 halfs = 128B = ONE cache
// line per row); per-NODE exp(-m) table.
__device__ __half g_rh[N_NODES * DIM];
__device__ float  g_xn[N_NODES];
// Monotonic ticket barrier (never reset -> safe across graph replays).
__device__ unsigned g_bar;

// Accumulate ||a-b||^2 contribution of one 16B chunk (8 halfs), fp32 math.
__device__ __forceinline__ float sq_chunk(const uint4& pa, const uint4& pb) {
    const __half2* ha = reinterpret_cast<const __half2*>(&pa);
    const __half2* hb = reinterpret_cast<const __half2*>(&pb);
    float acc = 0.0f;
    #pragma unroll
    for (int k = 0; k < 4; k++) {
        float2 fa = __half22float2(ha[k]);
        float2 fb = __half22float2(hb[k]);
        float dx = fa.x - fb.x;
        float dy = fa.y - fb.y;
        acc = fmaf(dx, dx, acc);
        acc = fmaf(dy, dy, acc);
    }
    return acc;
}

// ONE persistent kernel: phase 1 repacks z (fp16 rows + exp(-m) table),
// a device-wide ticket barrier, then phase 2 grid-strides warps over
// 16-edge tiles (the proven R16 gather/reduce engine). Fusing removes the
// second launch boundary + inter-kernel drain (~1.5-2.5us measured gap).
// Co-residency of all 888 blocks is guaranteed by __launch_bounds__(256,6).
// Every 128B line of g_rh/g_xn is written entirely by one warp and never
// read pre-barrier, so there is no stale-L1 hazard after the barrier.
__global__ void __launch_bounds__(BLK, BLOCKS_PER_SM) fused_kernel(
        const float* __restrict__ z,
        const int* __restrict__ eidx,
        const float* __restrict__ lptr,
        float4* __restrict__ out) {
    unsigned tid = blockIdx.x * BLK + threadIdx.x;

    // ---------------- Phase 1: repack ----------------
    const int quads = N_NODES * DIM / 4;   // 196608 (< 227328 threads)
    if (tid < (unsigned)quads) {
        int row = tid >> 4;          // 16 quads per 64-wide row
        int col = (tid & 15) << 2;
        const float* src = z + row * 65 + col;
        float x0 = src[0];
        float x1 = src[1];
        float x2 = src[2];
        float x3 = src[3];
        __half2 h0 = __floats2half2_rn(x0, x1);
        __half2 h1 = __floats2half2_rn(x2, x3);
        uint2 w;
        w.x = *reinterpret_cast<unsigned*>(&h0);
        w.y = *reinterpret_cast<unsigned*>(&h1);
        *reinterpret_cast<uint2*>(g_rh + (size_t)tid * 4) = w;
    }
    if (tid < N_NODES) {
        g_xn[tid] = __expf(-z[tid * 65 + 64]);
    }

    // ---------------- Grid-wide ticket barrier ----------------
    __threadfence();   // make phase-1 stores visible before arrival
    if (threadIdx.x == 0) {
        unsigned ticket = atomicAdd(&g_bar, 1u);
        unsigned tgt = (ticket / gridDim.x + 1u) * gridDim.x;
        volatile unsigned* vb = &g_bar;
        while (*vb < tgt) __nanosleep(64);
    }
    __syncthreads();
    __threadfence();   // order the spin-load before phase-2 loads

    // ---------------- Phase 2: edges ----------------
    unsigned lane = threadIdx.x & 31u;
    unsigned i    = lane & 7u;         // lane within 8-group
    unsigned grp  = lane >> 3;         // group 0..3
    unsigned wg   = blockIdx.x * (BLK / 32) + (threadIdx.x >> 5);
    unsigned nw   = gridDim.x * (BLK / 32);

    const uint4* __restrict__ rb = reinterpret_cast<const uint4*>(g_rh);
    float l = __ldg(lptr);

    for (unsigned tile = wg; tile < N_EDGES / 16; tile += nw) {
        unsigned base = tile * 16u;

        // Prologue: tail edge's node indices + exp(-m) gathers (consumed
        // after the two compute rounds; latency covered).
        unsigned e_mine = base + (lane & 15u);
        int u_mine = eidx[e_mine];
        int v_mine = eidx[N_EDGES + e_mine];
        float xu = g_xn[u_mine];
        float xv = g_xn[v_mine];

        float myacc = 0.0f;

        #pragma unroll
        for (unsigned r = 0; r < 2; r++) {
            unsigned e0 = base + r * 8u + grp * 2u;

            int2 uu = *reinterpret_cast<const int2*>(eidx + e0);
            int2 vv = *reinterpret_cast<const int2*>(eidx + N_EDGES + e0);

            uint4 pa0 = rb[uu.x * 8 + i];
            uint4 pb0 = rb[vv.x * 8 + i];
            uint4 pa1 = rb[uu.y * 8 + i];
            uint4 pb1 = rb[vv.y * 8 + i];

            float acc0 = sq_chunk(pa0, pb0);
            float acc1 = sq_chunk(pa1, pb1);

            acc0 += __shfl_xor_sync(0xffffffffu, acc0, 4);
            acc1 += __shfl_xor_sync(0xffffffffu, acc1, 4);
            acc0 += __shfl_xor_sync(0xffffffffu, acc0, 2);
            acc1 += __shfl_xor_sync(0xffffffffu, acc1, 2);
            acc0 += __shfl_xor_sync(0xffffffffu, acc0, 1);
            acc1 += __shfl_xor_sync(0xffffffffu, acc1, 1);

            unsigned src = (i >> 1) << 3;
            float va = __shfl_sync(0xffffffffu, acc0, src);
            float vb = __shfl_sync(0xffffffffu, acc1, src);
            float val = (i & 1u) ? vb : va;
            if (grp == r) myacc = val;     // predicated select
        }

        if (lane < 16u) {
            float E = __expf(l * __logf(myacc + EPS_F));   // (d2+eps)^l
            float x = E * xv;              // exp(-logit_uv)
            float y = E * xu;              // exp(-logit_vu)
            float rr = __fdividef(1.0f, (1.0f + x) * (1.0f + y));

            float4 o;
            o.x = x * y * rr;   // p_nb
            o.y = y * rr;       // p_pu
            o.z = rr;           // p_pb
            o.w = x * rr;       // p_nu
            out[e_mine] = o;    // coalesced STG.128
        }
    }
}

extern "C" void kernel_launch(void* const* d_in, const int* in_sizes, int n_in,
                              void* d_out, int out_size) {
    const float* z    = (const float*)d_in[0];
    const float* l    = (const float*)d_in[1];
    const int*   eidx = (const int*)d_in[2];   // int64 in reference, but JAX
                                               // x64 is disabled -> int32
    float4*      out  = (float4*)d_out;

    fused_kernel<<<GRID, BLK>>>(z, eidx, l, out);
}